// round 5
// baseline (speedup 1.0000x reference)
#include <cuda_runtime.h>
#include <cuda_bf16.h>
#include <cstdint>
#include <math.h>

#define BB 64
#define SS 512
#define II 256
#define HH 512
#define KTOT 768
#define G4 2048
#define KC 64
#define NCH 12                 // 768/64
#define NTILES 64              // 2048 permuted cols / 32
#define NCTAS 128

#define RSTRIDE 144            // padded row stride bytes (72 bf16)
// smem layout (dynamic):
//   [0, 55296)        B_hi  [12 ch][32 rows][72 bf16]
//   [55296, 110592)   B_lo
//   [110592, 147456)  A stages: 2 x (A_hi 9216 + A_lo 9216)
//   Gs (epilogue, 9216 B) aliases A stage 0
#define B_HI_OFF 0
#define B_LO_OFF 55296
#define A_OFF    110592
#define A_STAGE  18432
#define SMEM_DYN 147456

// ---------------- persistent device state ----------------
__device__ float g_c[2 * BB * HH];
__device__ __align__(16) __nv_bfloat16 g_h_hi[2 * 2 * BB * HH];   // [dir][parity][b][n]
__device__ __align__(16) __nv_bfloat16 g_h_lo[2 * 2 * BB * HH];
__device__ __align__(16) __nv_bfloat16 g_x_hi[(size_t)BB * SS * II];
__device__ __align__(16) __nv_bfloat16 g_x_lo[(size_t)BB * SS * II];
__device__ __align__(16) __nv_bfloat16 g_wt_hi[(size_t)2 * G4 * KTOT];  // [dir][prow][k]
__device__ __align__(16) __nv_bfloat16 g_wt_lo[(size_t)2 * G4 * KTOT];
__device__ __align__(16) float g_bias_p[2 * G4];                  // permuted bias
__device__ float g_hb[(size_t)BB * SS * HH];
__device__ unsigned g_bar_count;   // zero-init, returns to zero
__device__ unsigned g_bar_sense;   // zero-init, returns to zero (even # flips)

// ---------------- helpers ----------------
__device__ __forceinline__ uint32_t smem_u32(const void* p) {
    uint32_t a;
    asm("{ .reg .u64 t; cvta.to.shared.u64 t, %1; cvt.u32.u64 %0, t; }" : "=r"(a) : "l"(p));
    return a;
}
__device__ __forceinline__ void cp16(uint32_t dst, const void* src) {
    asm volatile("cp.async.cg.shared.global [%0], [%1], 16;" :: "r"(dst), "l"(src));
}
__device__ __forceinline__ void cp_commit() { asm volatile("cp.async.commit_group;"); }
__device__ __forceinline__ void cp_wait0()  { asm volatile("cp.async.wait_group 0;"); }
__device__ __forceinline__ void cp_wait1()  { asm volatile("cp.async.wait_group 1;"); }

__device__ __forceinline__ void ldm_x4(uint32_t* r, uint32_t addr) {
    asm volatile("ldmatrix.sync.aligned.m8n8.x4.shared.b16 {%0,%1,%2,%3}, [%4];"
                 : "=r"(r[0]), "=r"(r[1]), "=r"(r[2]), "=r"(r[3]) : "r"(addr));
}
__device__ __forceinline__ void ldm_x2(uint32_t* r, uint32_t addr) {
    asm volatile("ldmatrix.sync.aligned.m8n8.x2.shared.b16 {%0,%1}, [%2];"
                 : "=r"(r[0]), "=r"(r[1]) : "r"(addr));
}
__device__ __forceinline__ void mma16816(float* c, const uint32_t* a, const uint32_t* b) {
    asm volatile("mma.sync.aligned.m16n8k16.row.col.f32.bf16.bf16.f32 "
                 "{%0,%1,%2,%3}, {%4,%5,%6,%7}, {%8,%9}, {%0,%1,%2,%3};"
                 : "+f"(c[0]), "+f"(c[1]), "+f"(c[2]), "+f"(c[3])
                 : "r"(a[0]), "r"(a[1]), "r"(a[2]), "r"(a[3]), "r"(b[0]), "r"(b[1]));
}

// Sense-reversing grid barrier. All NCTAS CTAs are co-resident (1 CTA/SM by
// smem, grid 128 <= 148 SMs). Ends each kernel run with count=0, sense=0.
__device__ __forceinline__ void grid_barrier(unsigned s) {
    __syncthreads();
    if (threadIdx.x == 0) {
        __threadfence();
        unsigned n = atomicAdd(&g_bar_count, 1u);
        if (n == NCTAS - 1u) {
            g_bar_count = 0u;
            __threadfence();
            *(volatile unsigned*)&g_bar_sense = s;
        } else {
            while (*(volatile unsigned*)&g_bar_sense != s) {}
            __threadfence();
        }
    }
    __syncthreads();
}

// ---------------- prep kernels ----------------
__global__ void zero_state_kernel() {
    int idx = blockIdx.x * blockDim.x + threadIdx.x;  // 131072
    if (idx < 2 * 2 * BB * HH) {
        g_h_hi[idx] = __nv_bfloat16(0.f);
        g_h_lo[idx] = __nv_bfloat16(0.f);
    }
    if (idx < 2 * BB * HH) g_c[idx] = 0.0f;
}

__global__ void prep_x_kernel(const float* __restrict__ x) {
    size_t i = (size_t)blockIdx.x * blockDim.x + threadIdx.x;
    if (i >= (size_t)BB * SS * II) return;
    float v = x[i];
    __nv_bfloat16 h = __float2bfloat16_rn(v);
    g_x_hi[i] = h;
    g_x_lo[i] = __float2bfloat16_rn(v - __bfloat162float(h));
}

// W[k][gc] -> Wt[dir][prow = j*4+gate][k], gc = gate*512 + j
__global__ void prep_w_kernel(const float* __restrict__ W_f, const float* __restrict__ W_b) {
    int idx = blockIdx.x * blockDim.x + threadIdx.x;
    if (idx >= 2 * KTOT * G4) return;
    int dir = idx / (KTOT * G4);
    int rem = idx % (KTOT * G4);
    int k  = rem / G4;
    int gc = rem % G4;
    float w = (dir ? W_b : W_f)[rem];
    int gate = gc >> 9;
    int j    = gc & 511;
    int prow = j * 4 + gate;
    size_t d = ((size_t)dir * G4 + prow) * KTOT + k;
    __nv_bfloat16 h = __float2bfloat16_rn(w);
    g_wt_hi[d] = h;
    g_wt_lo[d] = __float2bfloat16_rn(w - __bfloat162float(h));
}

__global__ void prep_bias_kernel(const float* __restrict__ b_f, const float* __restrict__ b_b) {
    int idx = blockIdx.x * blockDim.x + threadIdx.x;
    if (idx >= 2 * G4) return;
    int dir = idx / G4;
    int gc  = idx % G4;
    int gate = gc >> 9, j = gc & 511;
    g_bias_p[dir * G4 + j * 4 + gate] = (dir ? b_b : b_f)[gc];
}

// ---------------- A-stage loader (activations only) ----------------
__device__ __forceinline__ void load_A(uint32_t smb, int buf, int ch,
                                       int tid, int dir, int p, int tx) {
    uint32_t base = smb + A_OFF + buf * A_STAGE;
    const int k0 = ch * KC;
#pragma unroll
    for (int i = 0; i < 2; i++) {
        int idx = tid + i * 256;          // 0..511
        int r = idx >> 3, q = idx & 7;
        uint32_t doff = r * RSTRIDE + q * 16;
        const __nv_bfloat16 *sh, *sl;
        if (k0 < II) {
            size_t so = ((size_t)r * SS + tx) * II + k0 + q * 8;
            sh = g_x_hi + so; sl = g_x_lo + so;
        } else {
            size_t so = ((size_t)(dir * 2 + p) * BB + r) * HH + (k0 - II) + q * 8;
            sh = g_h_hi + so; sl = g_h_lo + so;
        }
        cp16(base + doff, sh);
        cp16(base + 9216 + doff, sl);
    }
    cp_commit();
}

// ---------------- persistent kernel ----------------
// grid (64 tiles, 2 dirs) = 128 CTAs, 256 threads. Weights resident in smem;
// 512-timestep loop with grid barrier between steps.
__global__ void __launch_bounds__(256, 1) lstm_persistent(float* __restrict__ out) {
    extern __shared__ __align__(16) char sm[];
    const int tid  = threadIdx.x;
    const int lane = tid & 31;
    const int wid  = tid >> 5;
    const int wm   = wid & 3;       // 4 M slices of 16 rows
    const int wn   = wid >> 2;      // 2 N slices of 16 cols
    const int tile = blockIdx.x;
    const int dir  = blockIdx.y;
    const int n0 = tile * 32;       // permuted weight-row base
    const int j0 = tile * 8;        // hidden-col base
    const uint32_t smb = smem_u32(sm);

    // ---- load this CTA's weight slice into smem once (hi + lo, all chunks) ----
    for (int u = tid; u < NCH * 32 * 8; u += 256) {   // 3072 16B units per half
        int ch = u >> 8;
        int rem = u & 255;
        int r = rem >> 3, q = rem & 7;
        size_t so = ((size_t)dir * G4 + n0 + r) * KTOT + ch * KC + q * 8;
        uint32_t doff = (uint32_t)ch * 4608 + r * RSTRIDE + q * 16;
        cp16(smb + B_HI_OFF + doff, g_wt_hi + so);
        cp16(smb + B_LO_OFF + doff, g_wt_lo + so);
    }
    cp_commit();
    cp_wait0();
    __syncthreads();

    // bias registers for pointwise (2 float4 per thread)
    float4 bi0 = *(const float4*)&g_bias_p[dir * G4 + (j0 + ((tid + 0)   >> 6)) * 4];
    float4 bi1 = *(const float4*)&g_bias_p[dir * G4 + (j0 + ((tid + 256) >> 6)) * 4];

#pragma unroll 1
    for (int t = 0; t < SS; t++) {
        const int tx = dir ? (SS - 1 - t) : t;
        const int p  = t & 1;

        float acc[2][4];
#pragma unroll
        for (int nt = 0; nt < 2; nt++)
#pragma unroll
            for (int i = 0; i < 4; i++) acc[nt][i] = 0.0f;

        load_A(smb, 0, 0, tid, dir, p, tx);

#pragma unroll 1
        for (int ch = 0; ch < NCH; ch++) {
            if (ch + 1 < NCH) {
                load_A(smb, (ch + 1) & 1, ch + 1, tid, dir, p, tx);
                cp_wait1();
            } else {
                cp_wait0();
            }
            __syncthreads();

            const uint32_t Ab  = smb + A_OFF + (ch & 1) * A_STAGE;
            const uint32_t Bhb = smb + B_HI_OFF + (uint32_t)ch * 4608;
            const uint32_t Blb = smb + B_LO_OFF + (uint32_t)ch * 4608;
#pragma unroll
            for (int ks = 0; ks < 4; ks++) {
                uint32_t ah[4], al[4], bh[2][2], bl[2][2];
                uint32_t ad = Ab + (uint32_t)(wm * 16 + (lane & 15)) * RSTRIDE
                                 + (uint32_t)(ks * 16 + (lane >> 4) * 8) * 2;
                ldm_x4(ah, ad);
                ldm_x4(al, ad + 9216);
#pragma unroll
                for (int nt = 0; nt < 2; nt++) {
                    uint32_t boff = (uint32_t)(wn * 16 + nt * 8 + (lane & 7)) * RSTRIDE
                                  + (uint32_t)(ks * 16 + ((lane >> 3) & 1) * 8) * 2;
                    ldm_x2(bh[nt], Bhb + boff);
                    ldm_x2(bl[nt], Blb + boff);
                }
#pragma unroll
                for (int nt = 0; nt < 2; nt++) {
                    mma16816(acc[nt], ah, bh[nt]);
                    mma16816(acc[nt], al, bh[nt]);
                    mma16816(acc[nt], ah, bl[nt]);
                }
            }
            __syncthreads();
        }

        // ---- epilogue: gates to smem (aliases A stage 0; all cp.async drained) ----
        float* Gs = (float*)(sm + A_OFF);   // [64][36]
#pragma unroll
        for (int nt = 0; nt < 2; nt++) {
            int row = wm * 16 + (lane >> 2);
            int col = wn * 16 + nt * 8 + 2 * (lane & 3);
            *(float2*)&Gs[row * 36 + col]       = make_float2(acc[nt][0], acc[nt][1]);
            *(float2*)&Gs[(row + 8) * 36 + col] = make_float2(acc[nt][2], acc[nt][3]);
        }
        __syncthreads();

        // ---- pointwise LSTM update: 512 (b, j) elems, 2 per thread ----
#pragma unroll
        for (int r2 = 0; r2 < 2; r2++) {
            int e = tid + r2 * 256;       // 0..511
            int b = e & 63;
            int jl = e >> 6;              // 0..7
            float4 g  = *(float4*)&Gs[b * 36 + jl * 4];
            float4 bi = r2 ? bi1 : bi0;
            float fg = g.x + bi.x;
            float ig = g.y + bi.y;
            float og = g.z + bi.z;
            float gg = g.w + bi.w;
            float fs = 1.0f / (1.0f + __expf(-fg));
            float is = 1.0f / (1.0f + __expf(-ig));
            float os = 1.0f / (1.0f + __expf(-og));
            int n = j0 + jl;
            float cprev = g_c[(dir * BB + b) * HH + n];
            float cn = fs * cprev + is * tanhf(gg);
            float hn = os * tanhf(cn);
            g_c[(dir * BB + b) * HH + n] = cn;
            size_t hidx = ((size_t)(dir * 2 + (1 - p)) * BB + b) * HH + n;
            __nv_bfloat16 hh = __float2bfloat16_rn(hn);
            g_h_hi[hidx] = hh;
            g_h_lo[hidx] = __float2bfloat16_rn(hn - __bfloat162float(hh));
            size_t oi = ((size_t)b * SS + tx) * HH + n;
            if (dir == 0) out[oi]  = 0.5f * hn;
            else          g_hb[oi] = 0.5f * hn;
        }

        // h must be visible chip-wide before any CTA starts step t+1
        grid_barrier((t & 1) ^ 1u);
    }
}

// out = 0.5*hf + 0.5*hb
__global__ void combine_kernel(float* __restrict__ out) {
    size_t i = (size_t)blockIdx.x * blockDim.x + threadIdx.x;
    const size_t n4 = (size_t)BB * SS * HH / 4;
    if (i < n4) {
        float4 a = ((const float4*)out)[i];
        float4 b = ((const float4*)g_hb)[i];
        a.x += b.x; a.y += b.y; a.z += b.z; a.w += b.w;
        ((float4*)out)[i] = a;
    }
}

extern "C" void kernel_launch(void* const* d_in, const int* in_sizes, int n_in,
                              void* d_out, int out_size) {
    const float* x   = (const float*)d_in[0];
    const float* W_f = (const float*)d_in[1];
    const float* b_f = (const float*)d_in[2];
    const float* W_b = (const float*)d_in[3];
    const float* b_b = (const float*)d_in[4];
    float* out = (float*)d_out;

    cudaFuncSetAttribute((const void*)lstm_persistent,
                         cudaFuncAttributeMaxDynamicSharedMemorySize, SMEM_DYN);

    zero_state_kernel<<<512, 256>>>();
    {
        size_t nx = (size_t)BB * SS * II;
        prep_x_kernel<<<(unsigned)((nx + 255) / 256), 256>>>(x);
    }
    prep_w_kernel<<<(2 * KTOT * G4 + 255) / 256, 256>>>(W_f, W_b);
    prep_bias_kernel<<<(2 * G4 + 255) / 256, 256>>>(b_f, b_b);

    dim3 grid(NTILES, 2);
    lstm_persistent<<<grid, 256, SMEM_DYN>>>(out);

    const int n4 = BB * SS * HH / 4;
    combine_kernel<<<(n4 + 255) / 256, 256>>>(out);
}

// round 6
// speedup vs baseline: 1.0718x; 1.0718x over previous
#include <cuda_runtime.h>
#include <cuda_bf16.h>
#include <cstdint>
#include <math.h>

#define BB 64
#define SS 512
#define II 256
#define HH 512
#define KTOT 768
#define G4 2048
#define KC 64
#define NCH 12                 // 768/64  (chunks 0-3 = x, 4-11 = h)
#define NTILES 64
#define NCTAS 128

#define RSTRIDE 144            // padded row stride bytes (72 bf16)
// smem layout (dynamic):
//   [0, 55296)         B_hi  [12 ch][32 rows][72 bf16]
//   [55296, 110592)    B_lo
//   [110592, 165888)   A stages: 3 x 18432 (A_hi 9216 + A_lo 9216)
//   [165888, 175104)   Gs epilogue tile (separate: overlaps next prefetch safely)
#define B_HI_OFF 0
#define B_LO_OFF 55296
#define A_OFF    110592
#define A_STAGE  18432
#define GS_OFF   165888
#define SMEM_DYN 175104

// ---------------- persistent device state ----------------
__device__ float g_c[2 * BB * HH];
__device__ __align__(16) __nv_bfloat16 g_h_hi[2 * 2 * BB * HH];   // [dir][parity][b][n]
__device__ __align__(16) __nv_bfloat16 g_h_lo[2 * 2 * BB * HH];
__device__ __align__(16) __nv_bfloat16 g_x_hi[(size_t)BB * SS * II];
__device__ __align__(16) __nv_bfloat16 g_x_lo[(size_t)BB * SS * II];
__device__ __align__(16) __nv_bfloat16 g_wt_hi[(size_t)2 * G4 * KTOT];  // [dir][prow][k]
__device__ __align__(16) __nv_bfloat16 g_wt_lo[(size_t)2 * G4 * KTOT];
__device__ __align__(16) float g_bias_p[2 * G4];
__device__ float g_hb[(size_t)BB * SS * HH];
__device__ unsigned g_bar_count;            // reset each launch
__device__ volatile unsigned g_bar_epoch;   // reset each launch

// ---------------- helpers ----------------
__device__ __forceinline__ uint32_t smem_u32(const void* p) {
    uint32_t a;
    asm("{ .reg .u64 t; cvta.to.shared.u64 t, %1; cvt.u32.u64 %0, t; }" : "=r"(a) : "l"(p));
    return a;
}
__device__ __forceinline__ void cp16(uint32_t dst, const void* src) {
    asm volatile("cp.async.cg.shared.global [%0], [%1], 16;" :: "r"(dst), "l"(src));
}
__device__ __forceinline__ void cp_commit() { asm volatile("cp.async.commit_group;"); }
__device__ __forceinline__ void cp_wait0()  { asm volatile("cp.async.wait_group 0;"); }
__device__ __forceinline__ void cp_wait1()  { asm volatile("cp.async.wait_group 1;"); }

__device__ __forceinline__ void ldm_x4(uint32_t* r, uint32_t addr) {
    asm volatile("ldmatrix.sync.aligned.m8n8.x4.shared.b16 {%0,%1,%2,%3}, [%4];"
                 : "=r"(r[0]), "=r"(r[1]), "=r"(r[2]), "=r"(r[3]) : "r"(addr));
}
__device__ __forceinline__ void ldm_x2(uint32_t* r, uint32_t addr) {
    asm volatile("ldmatrix.sync.aligned.m8n8.x2.shared.b16 {%0,%1}, [%2];"
                 : "=r"(r[0]), "=r"(r[1]) : "r"(addr));
}
__device__ __forceinline__ void mma16816(float* c, const uint32_t* a, const uint32_t* b) {
    asm volatile("mma.sync.aligned.m16n8k16.row.col.f32.bf16.bf16.f32 "
                 "{%0,%1,%2,%3}, {%4,%5,%6,%7}, {%8,%9}, {%0,%1,%2,%3};"
                 : "+f"(c[0]), "+f"(c[1]), "+f"(c[2]), "+f"(c[3])
                 : "r"(a[0]), "r"(a[1]), "r"(a[2]), "r"(a[3]), "r"(b[0]), "r"(b[1]));
}

// ---------------- prep kernels ----------------
__global__ void zero_state_kernel() {
    int idx = blockIdx.x * blockDim.x + threadIdx.x;  // 131072
    if (idx < 2 * 2 * BB * HH) {
        g_h_hi[idx] = __nv_bfloat16(0.f);
        g_h_lo[idx] = __nv_bfloat16(0.f);
    }
    if (idx < 2 * BB * HH) g_c[idx] = 0.0f;
    if (idx == 0) { g_bar_count = 0u; g_bar_epoch = 0u; }
}

__global__ void prep_x_kernel(const float* __restrict__ x) {
    size_t i = (size_t)blockIdx.x * blockDim.x + threadIdx.x;
    if (i >= (size_t)BB * SS * II) return;
    float v = x[i];
    __nv_bfloat16 h = __float2bfloat16_rn(v);
    g_x_hi[i] = h;
    g_x_lo[i] = __float2bfloat16_rn(v - __bfloat162float(h));
}

// W[k][gc] -> Wt[dir][prow = j*4+gate][k], gc = gate*512 + j
__global__ void prep_w_kernel(const float* __restrict__ W_f, const float* __restrict__ W_b) {
    int idx = blockIdx.x * blockDim.x + threadIdx.x;
    if (idx >= 2 * KTOT * G4) return;
    int dir = idx / (KTOT * G4);
    int rem = idx % (KTOT * G4);
    int k  = rem / G4;
    int gc = rem % G4;
    float w = (dir ? W_b : W_f)[rem];
    int gate = gc >> 9;
    int j    = gc & 511;
    int prow = j * 4 + gate;
    size_t d = ((size_t)dir * G4 + prow) * KTOT + k;
    __nv_bfloat16 h = __float2bfloat16_rn(w);
    g_wt_hi[d] = h;
    g_wt_lo[d] = __float2bfloat16_rn(w - __bfloat162float(h));
}

__global__ void prep_bias_kernel(const float* __restrict__ b_f, const float* __restrict__ b_b) {
    int idx = blockIdx.x * blockDim.x + threadIdx.x;
    if (idx >= 2 * G4) return;
    int dir = idx / G4;
    int gc  = idx % G4;
    int gate = gc >> 9, j = gc & 511;
    g_bias_p[dir * G4 + j * 4 + gate] = (dir ? b_b : b_f)[gc];
}

// ---------------- A-stage loader (activations only) ----------------
__device__ __forceinline__ void load_A(uint32_t smb, int stage, int ch,
                                       int tid, int dir, int p, int tx) {
    uint32_t base = smb + A_OFF + stage * A_STAGE;
    const int k0 = ch * KC;
#pragma unroll
    for (int i = 0; i < 2; i++) {
        int idx = tid + i * 256;          // 0..511
        int r = idx >> 3, q = idx & 7;
        uint32_t doff = r * RSTRIDE + q * 16;
        const __nv_bfloat16 *sh, *sl;
        if (k0 < II) {
            size_t so = ((size_t)r * SS + tx) * II + k0 + q * 8;
            sh = g_x_hi + so; sl = g_x_lo + so;
        } else {
            size_t so = ((size_t)(dir * 2 + p) * BB + r) * HH + (k0 - II) + q * 8;
            sh = g_h_hi + so; sl = g_h_lo + so;
        }
        cp16(base + doff, sh);
        cp16(base + 9216 + doff, sl);
    }
    cp_commit();
}

// ---------------- chunk compute ----------------
__device__ __forceinline__ void compute_chunk(uint32_t smb, int stage, int ch,
                                              int lane, int wm, int wn, float acc[2][4]) {
    const uint32_t Ab  = smb + A_OFF + stage * A_STAGE;
    const uint32_t Bhb = smb + B_HI_OFF + (uint32_t)ch * 4608;
    const uint32_t Blb = smb + B_LO_OFF + (uint32_t)ch * 4608;
#pragma unroll
    for (int ks = 0; ks < 4; ks++) {
        uint32_t ah[4], al[4], bh[2][2], bl[2][2];
        uint32_t ad = Ab + (uint32_t)(wm * 16 + (lane & 15)) * RSTRIDE
                         + (uint32_t)(ks * 16 + (lane >> 4) * 8) * 2;
        ldm_x4(ah, ad);
        ldm_x4(al, ad + 9216);
#pragma unroll
        for (int nt = 0; nt < 2; nt++) {
            uint32_t boff = (uint32_t)(wn * 16 + nt * 8 + (lane & 7)) * RSTRIDE
                          + (uint32_t)(ks * 16 + ((lane >> 3) & 1) * 8) * 2;
            ldm_x2(bh[nt], Bhb + boff);
            ldm_x2(bl[nt], Blb + boff);
        }
#pragma unroll
        for (int nt = 0; nt < 2; nt++) {
            mma16816(acc[nt], ah, bh[nt]);
            mma16816(acc[nt], al, bh[nt]);
            mma16816(acc[nt], ah, bl[nt]);
        }
    }
}

// ---------------- persistent kernel ----------------
// grid (64 tiles, 2 dirs) = 128 CTAs, 256 threads, 1 CTA/SM (smem-bound).
// Split grid barrier: arrive after writing h(t), compute x-chunks of t+1,
// THEN wait — barrier latency hides behind 4 chunks of x-MMA work.
__global__ void __launch_bounds__(256, 1) lstm_persistent(float* __restrict__ out) {
    extern __shared__ __align__(16) char sm[];
    const int tid  = threadIdx.x;
    const int lane = tid & 31;
    const int wid  = tid >> 5;
    const int wm   = wid & 3;
    const int wn   = wid >> 2;
    const int tile = blockIdx.x;
    const int dir  = blockIdx.y;
    const int n0 = tile * 32;
    const int j0 = tile * 8;
    const uint32_t smb = smem_u32(sm);

    // ---- weights (hi+lo, all 12 chunks) resident in smem ----
    for (int u = tid; u < NCH * 32 * 8; u += 256) {
        int ch = u >> 8;
        int rem = u & 255;
        int r = rem >> 3, q = rem & 7;
        size_t so = ((size_t)dir * G4 + n0 + r) * KTOT + ch * KC + q * 8;
        uint32_t doff = (uint32_t)ch * 4608 + r * RSTRIDE + q * 16;
        cp16(smb + B_HI_OFF + doff, g_wt_hi + so);
        cp16(smb + B_LO_OFF + doff, g_wt_lo + so);
    }
    cp_commit();
    cp_wait0();
    __syncthreads();

    float4 bi0 = *(const float4*)&g_bias_p[dir * G4 + (j0 + ((tid + 0)   >> 6)) * 4];
    float4 bi1 = *(const float4*)&g_bias_p[dir * G4 + (j0 + ((tid + 256) >> 6)) * 4];

#pragma unroll 1
    for (int t = 0; t < SS; t++) {
        const int tx = dir ? (SS - 1 - t) : t;
        const int p  = t & 1;

        float acc[2][4];
#pragma unroll
        for (int nt = 0; nt < 2; nt++)
#pragma unroll
            for (int i = 0; i < 4; i++) acc[nt][i] = 0.0f;

        // ---- phase X: chunks 0-3 (input part, no h dependency) ----
        load_A(smb, 0, 0, tid, dir, p, tx);
        load_A(smb, 1, 1, tid, dir, p, tx);
#pragma unroll 1
        for (int ch = 0; ch < 4; ch++) {
            if (ch < 3) cp_wait1(); else cp_wait0();
            __syncthreads();
            // issue AFTER sync: stage (ch+2)%3's last readers (chunk ch-1) are done
            if (ch < 2) load_A(smb, (ch + 2) % 3, ch + 2, tid, dir, p, tx);
            compute_chunk(smb, ch % 3, ch, lane, wm, wn, acc);
        }

        // ---- barrier WAIT: all CTAs must have published h for parity p ----
        if (t > 0) {
            if (tid == 0) {
                while (g_bar_epoch < (unsigned)t) {}
                __threadfence();
            }
            __syncthreads();
        }

        // ---- phase H: chunks 4-11 (hidden part) ----
        load_A(smb, 4 % 3, 4, tid, dir, p, tx);
        load_A(smb, 5 % 3, 5, tid, dir, p, tx);
#pragma unroll 1
        for (int ch = 4; ch < 12; ch++) {
            if (ch < 11) cp_wait1(); else cp_wait0();
            __syncthreads();
            if (ch < 10) load_A(smb, (ch + 2) % 3, ch + 2, tid, dir, p, tx);
            compute_chunk(smb, ch % 3, ch, lane, wm, wn, acc);
        }

        // ---- epilogue: gates to smem (separate Gs region) ----
        float* Gs = (float*)(sm + GS_OFF);   // [64][36]
#pragma unroll
        for (int nt = 0; nt < 2; nt++) {
            int row = wm * 16 + (lane >> 2);
            int col = wn * 16 + nt * 8 + 2 * (lane & 3);
            *(float2*)&Gs[row * 36 + col]       = make_float2(acc[nt][0], acc[nt][1]);
            *(float2*)&Gs[(row + 8) * 36 + col] = make_float2(acc[nt][2], acc[nt][3]);
        }
        __syncthreads();

        // ---- pointwise LSTM update ----
#pragma unroll
        for (int r2 = 0; r2 < 2; r2++) {
            int e = tid + r2 * 256;
            int b = e & 63;
            int jl = e >> 6;
            float4 g  = *(float4*)&Gs[b * 36 + jl * 4];
            float4 bi = r2 ? bi1 : bi0;
            float fg = g.x + bi.x;
            float ig = g.y + bi.y;
            float og = g.z + bi.z;
            float gg = g.w + bi.w;
            float fs = 1.0f / (1.0f + __expf(-fg));
            float is = 1.0f / (1.0f + __expf(-ig));
            float os = 1.0f / (1.0f + __expf(-og));
            int n = j0 + jl;
            float cprev = g_c[(dir * BB + b) * HH + n];
            float cn = fs * cprev + is * tanhf(gg);
            float hn = os * tanhf(cn);
            g_c[(dir * BB + b) * HH + n] = cn;
            size_t hidx = ((size_t)(dir * 2 + (1 - p)) * BB + b) * HH + n;
            __nv_bfloat16 hh = __float2bfloat16_rn(hn);
            g_h_hi[hidx] = hh;
            g_h_lo[hidx] = __float2bfloat16_rn(hn - __bfloat162float(hh));
            size_t oi = ((size_t)b * SS + tx) * HH + n;
            if (dir == 0) out[oi]  = 0.5f * hn;
            else          g_hb[oi] = 0.5f * hn;
        }

        // ---- barrier ARRIVE (non-blocking): h(t) published ----
        __syncthreads();
        if (t < SS - 1 && tid == 0) {
            __threadfence();
            unsigned n = atomicAdd(&g_bar_count, 1u);
            if (n == NCTAS - 1u) {
                g_bar_count = 0u;
                __threadfence();
                g_bar_epoch = (unsigned)(t + 1);
            }
        }
        // no wait here — next iteration's x-phase runs before its wait
    }
}

// out = 0.5*hf + 0.5*hb
__global__ void combine_kernel(float* __restrict__ out) {
    size_t i = (size_t)blockIdx.x * blockDim.x + threadIdx.x;
    const size_t n4 = (size_t)BB * SS * HH / 4;
    if (i < n4) {
        float4 a = ((const float4*)out)[i];
        float4 b = ((const float4*)g_hb)[i];
        a.x += b.x; a.y += b.y; a.z += b.z; a.w += b.w;
        ((float4*)out)[i] = a;
    }
}

extern "C" void kernel_launch(void* const* d_in, const int* in_sizes, int n_in,
                              void* d_out, int out_size) {
    const float* x   = (const float*)d_in[0];
    const float* W_f = (const float*)d_in[1];
    const float* b_f = (const float*)d_in[2];
    const float* W_b = (const float*)d_in[3];
    const float* b_b = (const float*)d_in[4];
    float* out = (float*)d_out;

    cudaFuncSetAttribute((const void*)lstm_persistent,
                         cudaFuncAttributeMaxDynamicSharedMemorySize, SMEM_DYN);

    zero_state_kernel<<<512, 256>>>();
    {
        size_t nx = (size_t)BB * SS * II;
        prep_x_kernel<<<(unsigned)((nx + 255) / 256), 256>>>(x);
    }
    prep_w_kernel<<<(2 * KTOT * G4 + 255) / 256, 256>>>(W_f, W_b);
    prep_bias_kernel<<<(2 * G4 + 255) / 256, 256>>>(b_f, b_b);

    dim3 grid(NTILES, 2);
    lstm_persistent<<<grid, 256, SMEM_DYN>>>(out);

    const int n4 = BB * SS * HH / 4;
    combine_kernel<<<(n4 + 255) / 256, 256>>>(out);
}